// round 15
// baseline (speedup 1.0000x reference)
#include <cuda_runtime.h>
#include <cuda_bf16.h>
#include <cuda_fp16.h>

#define N_NODES 100000
#define N_EDGES 1250000
#define D_IN 64
#define D_HID 32
#define D_OUT 41
#define D_OUTP 44        // padded to multiple of 4 for LDS.128 weight loads
#define CAP 64           // padded adjacency capacity per node (max deg ~34)
#define OUT_BLK 128

typedef unsigned long long ull;

// ---------------- device scratch (static: no runtime allocation) ------------
// gathered tables (y1l, h) are fp16 rows of 64B with one extra ZERO row at
// index N_NODES (never written; zero-init) for branchless clamped gathers.
__device__ __align__(16) int      g_cnt[N_NODES];
__device__ __align__(16) int      g_adj[(size_t)N_NODES * CAP];   // 25.6 MB
__device__ __align__(16) __half   g_y1l[(N_NODES + 1) * D_HID];   // fp16 (+zero row)
__device__ __align__(16) float    g_y1r[N_NODES * D_HID];         // fp32
__device__ __align__(16) __half   g_h  [(N_NODES + 1) * D_HID];   // fp16 (+zero row)
__device__ __align__(16) float    g_agg2[N_NODES * D_HID];        // fp32

// ---------------- packed f32x2 / fp16 helpers --------------------------------
__device__ __forceinline__ ull fma2(ull a, ull b, ull c) {
    ull d;
    asm("fma.rn.f32x2 %0, %1, %2, %3;" : "=l"(d) : "l"(a), "l"(b), "l"(c));
    return d;
}
__device__ __forceinline__ ull pack2(float v) {
    ull r;
    asm("mov.b64 %0, {%1, %1};" : "=l"(r) : "f"(v));
    return r;
}
__device__ __forceinline__ void unpack2(ull p, float& lo, float& hi) {
    asm("mov.b64 {%0, %1}, %2;" : "=f"(lo), "=f"(hi) : "l"(p));
}
__device__ __forceinline__ __half2 u2h(unsigned u) {
    return *reinterpret_cast<__half2*>(&u);
}
__device__ __forceinline__ unsigned h2u(__half2 h) {
    return *reinterpret_cast<unsigned*>(&h);
}
__device__ __forceinline__ float2 h2f2(unsigned u) {
    __half2 h = *reinterpret_cast<__half2*>(&u);
    return __half22float2(h);
}
__device__ __forceinline__ unsigned f2h2(float lo, float hi) {
    __half2 h = __floats2half2_rn(lo, hi);
    return *reinterpret_cast<unsigned*>(&h);
}

// ---------------- adjacency build: single scatter pass ----------------------
__global__ void k_scatter(const int* __restrict__ ei) {
    int e = blockIdx.x * blockDim.x + threadIdx.x;
    if (e < N_EDGES) {
        int s = ei[e];
        int d = ei[N_EDGES + e];
        if ((unsigned)d < (unsigned)N_NODES && (unsigned)s < (unsigned)N_NODES) {
            int pos = atomicAdd(&g_cnt[d], 1);
            if (pos < CAP) g_adj[(size_t)d * CAP + pos] = s;
        }
    }
}

// ---------------- layer-1 dense transforms (f32x2 + LDS.128 weights) ---------
__global__ void __launch_bounds__(128) k_transform1(const float* __restrict__ x,
                             const float* __restrict__ W1l,
                             const float* __restrict__ W1r,
                             const float* __restrict__ b1) {
    __shared__ __align__(16) float sWl[D_IN * D_HID];
    __shared__ __align__(16) float sWr[D_IN * D_HID];
    __shared__ __align__(16) float sb[D_HID];
    for (int i = threadIdx.x; i < D_IN * D_HID; i += blockDim.x) {
        sWl[i] = W1l[i];
        sWr[i] = W1r[i];
    }
    if (threadIdx.x < D_HID) sb[threadIdx.x] = b1[threadIdx.x];
    __syncthreads();

    int n = blockIdx.x * blockDim.x + threadIdx.x;
    if (n >= N_NODES) return;

    ull accL[D_HID / 2];
    ull accR[D_HID / 2];
    const ull* sbp = reinterpret_cast<const ull*>(sb);
#pragma unroll
    for (int j = 0; j < D_HID / 2; j++) { accL[j] = 0ull; accR[j] = sbp[j]; }

    const float4* xr = reinterpret_cast<const float4*>(x + (size_t)n * D_IN);
#pragma unroll 4
    for (int kq = 0; kq < D_IN / 4; kq++) {
        float4 xv4 = xr[kq];
        float xv[4] = {xv4.x, xv4.y, xv4.z, xv4.w};
#pragma unroll
        for (int ki = 0; ki < 4; ki++) {
            int k = kq * 4 + ki;
            ull xv2 = pack2(xv[ki]);
            const ulonglong2* wl = reinterpret_cast<const ulonglong2*>(sWl + k * D_HID);
            const ulonglong2* wr = reinterpret_cast<const ulonglong2*>(sWr + k * D_HID);
#pragma unroll
            for (int j = 0; j < D_HID / 4; j++) {      // LDS.128: 2 fma2 per load
                ulonglong2 w1 = wl[j];
                ulonglong2 w2 = wr[j];
                accL[2 * j]     = fma2(xv2, w1.x, accL[2 * j]);
                accL[2 * j + 1] = fma2(xv2, w1.y, accL[2 * j + 1]);
                accR[2 * j]     = fma2(xv2, w2.x, accR[2 * j]);
                accR[2 * j + 1] = fma2(xv2, w2.y, accR[2 * j + 1]);
            }
        }
    }
    // y1l -> fp16 row (64B = 4 x uint4)
    unsigned hw[D_HID / 2];
#pragma unroll
    for (int j = 0; j < D_HID / 2; j++) {
        float lo, hi;
        unpack2(accL[j], lo, hi);
        hw[j] = f2h2(lo, hi);
    }
    uint4* oL = reinterpret_cast<uint4*>(g_y1l + (size_t)n * D_HID);
#pragma unroll
    for (int t = 0; t < 4; t++)
        oL[t] = make_uint4(hw[4 * t], hw[4 * t + 1], hw[4 * t + 2], hw[4 * t + 3]);

    // y1r stays fp32
    ulonglong2* outR = reinterpret_cast<ulonglong2*>(g_y1r + (size_t)n * D_HID);
#pragma unroll
    for (int jj = 0; jj < D_HID / 4; jj++) {
        ulonglong2 vr; vr.x = accR[2 * jj]; vr.y = accR[2 * jj + 1];
        outR[jj] = vr;
    }
}

// ---------------- branchless clamped gather, full-fp16 accumulate ------------
// Group g = lane>>3 owns contiguous slots [4g,4g+4) (tier1) and [16+4g,..)
// (tier2): adjacency comes in ONE int4 per tier. sub = lane&7 covers features
// [4*sub,4*sub+4) as one uint2 (4 halves). Invalid slots clamp (SEL) to the
// zero row at N_NODES. All accumulation in fp16 (HADD2 tree + fp16 shfl
// reduce; |sum|<200 << 65504); single convert to fp32 at the end.
__device__ __forceinline__ void gather_rows_sum_h(const __half* __restrict__ base,
                                                  const int* __restrict__ adj,
                                                  int cnt, int g, int sub,
                                                  float& a0, float& a1,
                                                  float& a2, float& a3) {
    const uint2* rows = reinterpret_cast<const uint2*>(base);
    __half2 hx, hy;
    {
        int4 av = *reinterpret_cast<const int4*>(adj + 4 * g);
        int s = 4 * g;
        unsigned r0 = (unsigned)((s     < cnt) ? av.x : N_NODES) * 8u + sub;
        unsigned r1 = (unsigned)((s + 1 < cnt) ? av.y : N_NODES) * 8u + sub;
        unsigned r2 = (unsigned)((s + 2 < cnt) ? av.z : N_NODES) * 8u + sub;
        unsigned r3 = (unsigned)((s + 3 < cnt) ? av.w : N_NODES) * 8u + sub;
        uint2 v0 = rows[r0], v1 = rows[r1], v2 = rows[r2], v3 = rows[r3];
        hx = __hadd2(__hadd2(u2h(v0.x), u2h(v1.x)), __hadd2(u2h(v2.x), u2h(v3.x)));
        hy = __hadd2(__hadd2(u2h(v0.y), u2h(v1.y)), __hadd2(u2h(v2.y), u2h(v3.y)));
    }
    if (cnt > 16) {   // warp-uniform
        int4 av = *reinterpret_cast<const int4*>(adj + 16 + 4 * g);
        int s = 16 + 4 * g;
        unsigned r0 = (unsigned)((s     < cnt) ? av.x : N_NODES) * 8u + sub;
        unsigned r1 = (unsigned)((s + 1 < cnt) ? av.y : N_NODES) * 8u + sub;
        unsigned r2 = (unsigned)((s + 2 < cnt) ? av.z : N_NODES) * 8u + sub;
        unsigned r3 = (unsigned)((s + 3 < cnt) ? av.w : N_NODES) * 8u + sub;
        uint2 v0 = rows[r0], v1 = rows[r1], v2 = rows[r2], v3 = rows[r3];
        hx = __hadd2(hx, __hadd2(__hadd2(u2h(v0.x), u2h(v1.x)),
                                 __hadd2(u2h(v2.x), u2h(v3.x))));
        hy = __hadd2(hy, __hadd2(__hadd2(u2h(v0.y), u2h(v1.y)),
                                 __hadd2(u2h(v2.y), u2h(v3.y))));
    }
    if (cnt > 32) {   // extreme tail, warp-uniform
        for (int e = 32 + g; e < cnt; e += 4) {
            uint2 v = rows[(unsigned)adj[e] * 8u + sub];
            hx = __hadd2(hx, u2h(v.x));
            hy = __hadd2(hy, u2h(v.y));
        }
    }
    // fp16 cross-group reduce (32-bit shuffles on packed half2)
    unsigned ux = h2u(hx), uy = h2u(hy);
#pragma unroll
    for (int off = 8; off < 32; off <<= 1) {
        ux = h2u(__hadd2(u2h(ux), u2h(__shfl_xor_sync(0xffffffffu, ux, off))));
        uy = h2u(__hadd2(u2h(uy), u2h(__shfl_xor_sync(0xffffffffu, uy, off))));
    }
    float2 fx = h2f2(ux);
    float2 fy = h2f2(uy);
    a0 = fx.x; a1 = fx.y; a2 = fy.x; a3 = fy.y;
}

// LAYER1: h = relu(mean_agg(y1l) + y1r)   (h stored fp16)
__global__ void k_aggregate1() {
    int warp = (blockIdx.x * blockDim.x + threadIdx.x) >> 5;
    int lane = threadIdx.x & 31;
    if (warp >= N_NODES) return;
    int g = lane >> 3, sub = lane & 7;
    int cnt = min(g_cnt[warp], CAP);
    float a0, a1, a2, a3;
    gather_rows_sum_h(g_y1l, g_adj + (size_t)warp * CAP, cnt, g, sub, a0, a1, a2, a3);
    float inv = 1.0f / fmaxf((float)cnt, 1.0f);
    if (g == 0) {
        float4 r = reinterpret_cast<const float4*>(g_y1r)[(size_t)warp * 8 + sub];
        float h0 = fmaxf(fmaf(a0, inv, r.x), 0.f);
        float h1 = fmaxf(fmaf(a1, inv, r.y), 0.f);
        float h2v = fmaxf(fmaf(a2, inv, r.z), 0.f);
        float h3 = fmaxf(fmaf(a3, inv, r.w), 0.f);
        uint2 st;
        st.x = f2h2(h0, h1);
        st.y = f2h2(h2v, h3);
        reinterpret_cast<uint2*>(g_h)[(size_t)warp * 8 + sub] = st;
    }
}

// LAYER2a: agg2 = mean_agg(h)   (agg2 stays fp32)
__global__ void k_aggregate2() {
    int warp = (blockIdx.x * blockDim.x + threadIdx.x) >> 5;
    int lane = threadIdx.x & 31;
    if (warp >= N_NODES) return;
    int g = lane >> 3, sub = lane & 7;
    int cnt = min(g_cnt[warp], CAP);
    float a0, a1, a2, a3;
    gather_rows_sum_h(g_h, g_adj + (size_t)warp * CAP, cnt, g, sub, a0, a1, a2, a3);
    float inv = 1.0f / fmaxf((float)cnt, 1.0f);
    if (g == 0) {
        float4 av;
        av.x = a0 * inv; av.y = a1 * inv; av.z = a2 * inv; av.w = a3 * inv;
        reinterpret_cast<float4*>(g_agg2)[(size_t)warp * 8 + sub] = av;
    }
}

// LAYER2b: out = agg2 @ W2l + h @ W2r + b2 (thread per node, f32x2 packed,
// LDS.128 weight loads; h read as fp16; smem-staged coalesced stores).
__global__ void __launch_bounds__(OUT_BLK) k_out(const float* __restrict__ W2l,
                      const float* __restrict__ W2r,
                      const float* __restrict__ b2,
                      float* __restrict__ out) {
    __shared__ __align__(16) float sWl[D_HID * D_OUTP];
    __shared__ __align__(16) float sWr[D_HID * D_OUTP];
    __shared__ __align__(16) float sb[D_OUTP];
    __shared__ __align__(16) float sOut[OUT_BLK * D_OUT];  // 21 KB

    for (int i = threadIdx.x; i < D_HID * D_OUTP; i += blockDim.x) {
        int k = i / D_OUTP, j = i % D_OUTP;
        sWl[i] = (j < D_OUT) ? W2l[k * D_OUT + j] : 0.0f;
        sWr[i] = (j < D_OUT) ? W2r[k * D_OUT + j] : 0.0f;
    }
    if (threadIdx.x < D_OUTP) sb[threadIdx.x] = (threadIdx.x < D_OUT) ? b2[threadIdx.x] : 0.0f;
    __syncthreads();

    int n = blockIdx.x * blockDim.x + threadIdx.x;
    bool valid = (n < N_NODES);

    if (valid) {
        ull acc[D_OUTP / 2];
        const ull* sb2 = reinterpret_cast<const ull*>(sb);
#pragma unroll
        for (int jp = 0; jp < D_OUTP / 2; jp++) acc[jp] = sb2[jp];

        const float4* ar = reinterpret_cast<const float4*>(g_agg2 + (size_t)n * D_HID);
        // h row: 64B = 4 x uint4 of halves
        unsigned hu[D_HID / 2];
        {
            const uint4* hr = reinterpret_cast<const uint4*>(g_h + (size_t)n * D_HID);
#pragma unroll
            for (int t = 0; t < 4; t++) {
                uint4 v = hr[t];
                hu[4 * t] = v.x; hu[4 * t + 1] = v.y;
                hu[4 * t + 2] = v.z; hu[4 * t + 3] = v.w;
            }
        }

#pragma unroll 2
        for (int kq = 0; kq < D_HID / 4; kq++) {
            float4 a4 = ar[kq];
            float a[4] = {a4.x, a4.y, a4.z, a4.w};
            float2 fA = h2f2(hu[2 * kq]);
            float2 fB = h2f2(hu[2 * kq + 1]);
            float hh[4] = {fA.x, fA.y, fB.x, fB.y};
#pragma unroll
            for (int ki = 0; ki < 4; ki++) {
                int k = kq * 4 + ki;
                ull a2v = pack2(a[ki]);
                ull h2v = pack2(hh[ki]);
                const ulonglong2* wl = reinterpret_cast<const ulonglong2*>(sWl + k * D_OUTP);
                const ulonglong2* wr = reinterpret_cast<const ulonglong2*>(sWr + k * D_OUTP);
#pragma unroll
                for (int jp = 0; jp < D_OUTP / 4; jp++) {   // LDS.128: 2 fma2 per load
                    ulonglong2 w1 = wl[jp];
                    ulonglong2 w2 = wr[jp];
                    acc[2 * jp]     = fma2(a2v, w1.x, acc[2 * jp]);
                    acc[2 * jp + 1] = fma2(a2v, w1.y, acc[2 * jp + 1]);
                    acc[2 * jp]     = fma2(h2v, w2.x, acc[2 * jp]);
                    acc[2 * jp + 1] = fma2(h2v, w2.y, acc[2 * jp + 1]);
                }
            }
        }
        float* row = sOut + threadIdx.x * D_OUT;
#pragma unroll
        for (int jp = 0; jp < D_OUT / 2; jp++) {
            float lo, hi;
            unpack2(acc[jp], lo, hi);
            row[2 * jp] = lo;
            row[2 * jp + 1] = hi;
        }
        {
            float lo, hi;
            unpack2(acc[D_OUT / 2], lo, hi);
            row[D_OUT - 1] = lo;   // j = 40
        }
    }
    __syncthreads();

    int nvalid = min(OUT_BLK, N_NODES - blockIdx.x * OUT_BLK);
    int nfl = nvalid * D_OUT;
    float4* dst = reinterpret_cast<float4*>(out + (size_t)blockIdx.x * OUT_BLK * D_OUT);
    const float4* src = reinterpret_cast<const float4*>(sOut);
    for (int i = threadIdx.x; i < (nfl >> 2); i += blockDim.x)
        dst[i] = src[i];
    for (int i = (nfl & ~3) + threadIdx.x; i < nfl; i += blockDim.x)
        out[(size_t)blockIdx.x * OUT_BLK * D_OUT + i] = sOut[i];
}

// ---------------- launch ------------------------------------------------------
extern "C" void kernel_launch(void* const* d_in, const int* in_sizes, int n_in,
                              void* d_out, int out_size) {
    const float* x   = (const float*)d_in[0];
    const int*   ei  = (const int*)d_in[1];   // int32 [2, E]
    const float* W1l = (const float*)d_in[2];
    const float* b1  = (const float*)d_in[3];
    const float* W1r = (const float*)d_in[4];
    const float* W2l = (const float*)d_in[5];
    const float* b2  = (const float*)d_in[6];
    const float* W2r = (const float*)d_in[7];
    float* out = (float*)d_out;

    static cudaStream_t s_side = nullptr;
    static cudaEvent_t  ev_fork = nullptr;
    static cudaEvent_t  ev_join = nullptr;
    if (s_side == nullptr) {
        cudaStreamCreateWithFlags(&s_side, cudaStreamNonBlocking);
        cudaEventCreateWithFlags(&ev_fork, cudaEventDisableTiming);
        cudaEventCreateWithFlags(&ev_join, cudaEventDisableTiming);
    }

    void* cnt_ptr = nullptr;
    cudaGetSymbolAddress(&cnt_ptr, g_cnt);
    cudaMemsetAsync(cnt_ptr, 0, N_NODES * sizeof(int), 0);

    // fork: transform1 (independent of adjacency build) on the side stream
    cudaEventRecord(ev_fork, 0);
    cudaStreamWaitEvent(s_side, ev_fork, 0);
    k_transform1<<<(N_NODES + 127) / 128, 128, 0, s_side>>>(x, W1l, W1r, b1);
    cudaEventRecord(ev_join, s_side);

    // adjacency build: one scatter pass (counts + padded adjacency)
    k_scatter<<<(N_EDGES + 255) / 256, 256>>>(ei);

    // join: aggregation needs both adjacency and y1l/y1r
    cudaStreamWaitEvent(0, ev_join, 0);
    k_aggregate1<<<(N_NODES * 32 + 255) / 256, 256>>>();

    // Layer 2: gather, then thread-per-node packed GEMV
    k_aggregate2<<<(N_NODES * 32 + 255) / 256, 256>>>();
    k_out<<<(N_NODES + OUT_BLK - 1) / OUT_BLK, OUT_BLK>>>(W2l, W2r, b2, out);
}

// round 16
// speedup vs baseline: 1.0256x; 1.0256x over previous
#include <cuda_runtime.h>
#include <cuda_bf16.h>
#include <cuda_fp16.h>

#define N_NODES 100000
#define N_EDGES 1250000
#define D_IN 64
#define D_HID 32
#define D_OUT 41
#define D_OUTP 44        // padded to multiple of 4 for LDS.128 weight loads
#define CAP 64           // padded adjacency capacity per node (max deg ~34)
#define OUT_BLK 128

typedef unsigned long long ull;

// ---------------- device scratch (static: no runtime allocation) ------------
// ALL node tables are fp16 rows of 64B. y1l/h have one extra ZERO row at index
// N_NODES (never written; zero-init) for branchless clamped gathers.
__device__ __align__(16) int      g_cnt[N_NODES];
__device__ __align__(16) int      g_adj[(size_t)N_NODES * CAP];   // 25.6 MB
__device__ __align__(16) __half   g_y1l[(N_NODES + 1) * D_HID];   // fp16 (+zero row)
__device__ __align__(16) __half   g_y1r[N_NODES * D_HID];         // fp16
__device__ __align__(16) __half   g_h  [(N_NODES + 1) * D_HID];   // fp16 (+zero row)
__device__ __align__(16) __half   g_agg2[N_NODES * D_HID];        // fp16

// ---------------- packed f32x2 / fp16 helpers --------------------------------
__device__ __forceinline__ ull fma2(ull a, ull b, ull c) {
    ull d;
    asm("fma.rn.f32x2 %0, %1, %2, %3;" : "=l"(d) : "l"(a), "l"(b), "l"(c));
    return d;
}
__device__ __forceinline__ ull pack2(float v) {
    ull r;
    asm("mov.b64 %0, {%1, %1};" : "=l"(r) : "f"(v));
    return r;
}
__device__ __forceinline__ void unpack2(ull p, float& lo, float& hi) {
    asm("mov.b64 {%0, %1}, %2;" : "=f"(lo), "=f"(hi) : "l"(p));
}
__device__ __forceinline__ __half2 u2h(unsigned u) {
    return *reinterpret_cast<__half2*>(&u);
}
__device__ __forceinline__ unsigned h2u(__half2 h) {
    return *reinterpret_cast<unsigned*>(&h);
}
__device__ __forceinline__ float2 h2f2(unsigned u) {
    __half2 h = *reinterpret_cast<__half2*>(&u);
    return __half22float2(h);
}
__device__ __forceinline__ unsigned f2h2(float lo, float hi) {
    __half2 h = __floats2half2_rn(lo, hi);
    return *reinterpret_cast<unsigned*>(&h);
}

// ---------------- adjacency build: single scatter pass ----------------------
// g_cnt arrives zeroed (zero-init on first run; k_out epilogue re-zeroes it
// at the end of every run, including the correctness run before capture).
__global__ void k_scatter(const int* __restrict__ ei) {
    int e = blockIdx.x * blockDim.x + threadIdx.x;
    if (e < N_EDGES) {
        int s = ei[e];
        int d = ei[N_EDGES + e];
        if ((unsigned)d < (unsigned)N_NODES && (unsigned)s < (unsigned)N_NODES) {
            int pos = atomicAdd(&g_cnt[d], 1);
            if (pos < CAP) g_adj[(size_t)d * CAP + pos] = s;
        }
    }
}

// ---------------- layer-1 dense transforms (f32x2 packed) --------------------
__global__ void __launch_bounds__(128) k_transform1(const float* __restrict__ x,
                             const float* __restrict__ W1l,
                             const float* __restrict__ W1r,
                             const float* __restrict__ b1) {
    __shared__ __align__(16) float sWl[D_IN * D_HID];
    __shared__ __align__(16) float sWr[D_IN * D_HID];
    __shared__ __align__(16) float sb[D_HID];
    for (int i = threadIdx.x; i < D_IN * D_HID; i += blockDim.x) {
        sWl[i] = W1l[i];
        sWr[i] = W1r[i];
    }
    if (threadIdx.x < D_HID) sb[threadIdx.x] = b1[threadIdx.x];
    __syncthreads();

    int n = blockIdx.x * blockDim.x + threadIdx.x;
    if (n >= N_NODES) return;

    ull accL[D_HID / 2];
    ull accR[D_HID / 2];
    const ull* sbp = reinterpret_cast<const ull*>(sb);
#pragma unroll
    for (int j = 0; j < D_HID / 2; j++) { accL[j] = 0ull; accR[j] = sbp[j]; }

    const float4* xr = reinterpret_cast<const float4*>(x + (size_t)n * D_IN);
#pragma unroll 4
    for (int kq = 0; kq < D_IN / 4; kq++) {
        float4 xv4 = xr[kq];
        float xv[4] = {xv4.x, xv4.y, xv4.z, xv4.w};
#pragma unroll
        for (int ki = 0; ki < 4; ki++) {
            int k = kq * 4 + ki;
            ull xv2 = pack2(xv[ki]);
            const ulonglong2* wl = reinterpret_cast<const ulonglong2*>(sWl + k * D_HID);
            const ulonglong2* wr = reinterpret_cast<const ulonglong2*>(sWr + k * D_HID);
#pragma unroll
            for (int j = 0; j < D_HID / 4; j++) {
                ulonglong2 w1 = wl[j];
                ulonglong2 w2 = wr[j];
                accL[2 * j]     = fma2(xv2, w1.x, accL[2 * j]);
                accL[2 * j + 1] = fma2(xv2, w1.y, accL[2 * j + 1]);
                accR[2 * j]     = fma2(xv2, w2.x, accR[2 * j]);
                accR[2 * j + 1] = fma2(xv2, w2.y, accR[2 * j + 1]);
            }
        }
    }
    // both outputs -> fp16 rows (64B = 4 x uint4)
    unsigned hl[D_HID / 2], hr[D_HID / 2];
#pragma unroll
    for (int j = 0; j < D_HID / 2; j++) {
        float lo, hi;
        unpack2(accL[j], lo, hi);
        hl[j] = f2h2(lo, hi);
        unpack2(accR[j], lo, hi);
        hr[j] = f2h2(lo, hi);
    }
    uint4* oL = reinterpret_cast<uint4*>(g_y1l + (size_t)n * D_HID);
    uint4* oR = reinterpret_cast<uint4*>(g_y1r + (size_t)n * D_HID);
#pragma unroll
    for (int t = 0; t < 4; t++) {
        oL[t] = make_uint4(hl[4 * t], hl[4 * t + 1], hl[4 * t + 2], hl[4 * t + 3]);
        oR[t] = make_uint4(hr[4 * t], hr[4 * t + 1], hr[4 * t + 2], hr[4 * t + 3]);
    }
}

// ---------------- branchless clamped gather, full-fp16 accumulate ------------
// Group g = lane>>3 owns contiguous slots [4g,4g+4) (tier1) and [16+4g,..)
// (tier2). Both tiers' int4 adjacency loads issue up front (independent of
// cnt) so tier2 never waits a second L2 round trip. Invalid slots clamp (SEL)
// to the zero row at N_NODES. fp16 accumulation throughout; single convert.
__device__ __forceinline__ void gather_rows_sum_h(const __half* __restrict__ base,
                                                  const int* __restrict__ adj,
                                                  int cnt, int g, int sub,
                                                  float& a0, float& a1,
                                                  float& a2, float& a3) {
    const uint2* rows = reinterpret_cast<const uint2*>(base);
    int4 av1 = *reinterpret_cast<const int4*>(adj + 4 * g);        // tier1 slots
    int4 av2 = *reinterpret_cast<const int4*>(adj + 16 + 4 * g);   // tier2 prefetch
    __half2 hx, hy;
    {
        int s = 4 * g;
        unsigned r0 = (unsigned)((s     < cnt) ? av1.x : N_NODES) * 8u + sub;
        unsigned r1 = (unsigned)((s + 1 < cnt) ? av1.y : N_NODES) * 8u + sub;
        unsigned r2 = (unsigned)((s + 2 < cnt) ? av1.z : N_NODES) * 8u + sub;
        unsigned r3 = (unsigned)((s + 3 < cnt) ? av1.w : N_NODES) * 8u + sub;
        uint2 v0 = rows[r0], v1 = rows[r1], v2 = rows[r2], v3 = rows[r3];
        hx = __hadd2(__hadd2(u2h(v0.x), u2h(v1.x)), __hadd2(u2h(v2.x), u2h(v3.x)));
        hy = __hadd2(__hadd2(u2h(v0.y), u2h(v1.y)), __hadd2(u2h(v2.y), u2h(v3.y)));
    }
    if (cnt > 16) {   // warp-uniform
        int s = 16 + 4 * g;
        unsigned r0 = (unsigned)((s     < cnt) ? av2.x : N_NODES) * 8u + sub;
        unsigned r1 = (unsigned)((s + 1 < cnt) ? av2.y : N_NODES) * 8u + sub;
        unsigned r2 = (unsigned)((s + 2 < cnt) ? av2.z : N_NODES) * 8u + sub;
        unsigned r3 = (unsigned)((s + 3 < cnt) ? av2.w : N_NODES) * 8u + sub;
        uint2 v0 = rows[r0], v1 = rows[r1], v2 = rows[r2], v3 = rows[r3];
        hx = __hadd2(hx, __hadd2(__hadd2(u2h(v0.x), u2h(v1.x)),
                                 __hadd2(u2h(v2.x), u2h(v3.x))));
        hy = __hadd2(hy, __hadd2(__hadd2(u2h(v0.y), u2h(v1.y)),
                                 __hadd2(u2h(v2.y), u2h(v3.y))));
    }
    if (cnt > 32) {   // extreme tail, warp-uniform
        for (int e = 32 + g; e < cnt; e += 4) {
            uint2 v = rows[(unsigned)adj[e] * 8u + sub];
            hx = __hadd2(hx, u2h(v.x));
            hy = __hadd2(hy, u2h(v.y));
        }
    }
    unsigned ux = h2u(hx), uy = h2u(hy);
#pragma unroll
    for (int off = 8; off < 32; off <<= 1) {
        ux = h2u(__hadd2(u2h(ux), u2h(__shfl_xor_sync(0xffffffffu, ux, off))));
        uy = h2u(__hadd2(u2h(uy), u2h(__shfl_xor_sync(0xffffffffu, uy, off))));
    }
    float2 fx = h2f2(ux);
    float2 fy = h2f2(uy);
    a0 = fx.x; a1 = fx.y; a2 = fy.x; a3 = fy.y;
}

// LAYER1: h = relu(mean_agg(y1l) + y1r)   (all fp16 tables)
__global__ void k_aggregate1() {
    int warp = (blockIdx.x * blockDim.x + threadIdx.x) >> 5;
    int lane = threadIdx.x & 31;
    if (warp >= N_NODES) return;
    int g = lane >> 3, sub = lane & 7;
    int cnt = min(g_cnt[warp], CAP);
    float a0, a1, a2, a3;
    gather_rows_sum_h(g_y1l, g_adj + (size_t)warp * CAP, cnt, g, sub, a0, a1, a2, a3);
    float inv = 1.0f / fmaxf((float)cnt, 1.0f);
    if (g == 0) {
        uint2 rv = reinterpret_cast<const uint2*>(g_y1r)[(size_t)warp * 8 + sub];
        float2 r01 = h2f2(rv.x);
        float2 r23 = h2f2(rv.y);
        float h0 = fmaxf(fmaf(a0, inv, r01.x), 0.f);
        float h1 = fmaxf(fmaf(a1, inv, r01.y), 0.f);
        float h2v = fmaxf(fmaf(a2, inv, r23.x), 0.f);
        float h3 = fmaxf(fmaf(a3, inv, r23.y), 0.f);
        uint2 st;
        st.x = f2h2(h0, h1);
        st.y = f2h2(h2v, h3);
        reinterpret_cast<uint2*>(g_h)[(size_t)warp * 8 + sub] = st;
    }
}

// LAYER2a: agg2 = mean_agg(h)   (agg2 stored fp16)
__global__ void k_aggregate2() {
    int warp = (blockIdx.x * blockDim.x + threadIdx.x) >> 5;
    int lane = threadIdx.x & 31;
    if (warp >= N_NODES) return;
    int g = lane >> 3, sub = lane & 7;
    int cnt = min(g_cnt[warp], CAP);
    float a0, a1, a2, a3;
    gather_rows_sum_h(g_h, g_adj + (size_t)warp * CAP, cnt, g, sub, a0, a1, a2, a3);
    float inv = 1.0f / fmaxf((float)cnt, 1.0f);
    if (g == 0) {
        uint2 st;
        st.x = f2h2(a0 * inv, a1 * inv);
        st.y = f2h2(a2 * inv, a3 * inv);
        reinterpret_cast<uint2*>(g_agg2)[(size_t)warp * 8 + sub] = st;
    }
}

// LAYER2b: out = agg2 @ W2l + h @ W2r + b2 (thread per node, f32x2 packed,
// agg2/h read as fp16; smem-staged coalesced stores). Epilogue zeroes g_cnt
// for the next run (replaces the memset graph node).
__global__ void __launch_bounds__(OUT_BLK) k_out(const float* __restrict__ W2l,
                      const float* __restrict__ W2r,
                      const float* __restrict__ b2,
                      float* __restrict__ out) {
    __shared__ __align__(16) float sWl[D_HID * D_OUTP];
    __shared__ __align__(16) float sWr[D_HID * D_OUTP];
    __shared__ __align__(16) float sb[D_OUTP];
    __shared__ __align__(16) float sOut[OUT_BLK * D_OUT];  // 21 KB

    for (int i = threadIdx.x; i < D_HID * D_OUTP; i += blockDim.x) {
        int k = i / D_OUTP, j = i % D_OUTP;
        sWl[i] = (j < D_OUT) ? W2l[k * D_OUT + j] : 0.0f;
        sWr[i] = (j < D_OUT) ? W2r[k * D_OUT + j] : 0.0f;
    }
    if (threadIdx.x < D_OUTP) sb[threadIdx.x] = (threadIdx.x < D_OUT) ? b2[threadIdx.x] : 0.0f;
    __syncthreads();

    int n = blockIdx.x * blockDim.x + threadIdx.x;
    bool valid = (n < N_NODES);

    if (valid) {
        ull acc[D_OUTP / 2];
        const ull* sb2 = reinterpret_cast<const ull*>(sb);
#pragma unroll
        for (int jp = 0; jp < D_OUTP / 2; jp++) acc[jp] = sb2[jp];

        // agg2 + h rows: each 64B = 4 x uint4 of halves
        unsigned au[D_HID / 2], hu[D_HID / 2];
        {
            const uint4* arp = reinterpret_cast<const uint4*>(g_agg2 + (size_t)n * D_HID);
            const uint4* hrp = reinterpret_cast<const uint4*>(g_h + (size_t)n * D_HID);
#pragma unroll
            for (int t = 0; t < 4; t++) {
                uint4 va = arp[t];
                uint4 vh = hrp[t];
                au[4 * t] = va.x; au[4 * t + 1] = va.y;
                au[4 * t + 2] = va.z; au[4 * t + 3] = va.w;
                hu[4 * t] = vh.x; hu[4 * t + 1] = vh.y;
                hu[4 * t + 2] = vh.z; hu[4 * t + 3] = vh.w;
            }
        }

#pragma unroll 2
        for (int kq = 0; kq < D_HID / 4; kq++) {
            float2 aA = h2f2(au[2 * kq]);
            float2 aB = h2f2(au[2 * kq + 1]);
            float a[4] = {aA.x, aA.y, aB.x, aB.y};
            float2 fA = h2f2(hu[2 * kq]);
            float2 fB = h2f2(hu[2 * kq + 1]);
            float hh[4] = {fA.x, fA.y, fB.x, fB.y};
#pragma unroll
            for (int ki = 0; ki < 4; ki++) {
                int k = kq * 4 + ki;
                ull a2v = pack2(a[ki]);
                ull h2v = pack2(hh[ki]);
                const ulonglong2* wl = reinterpret_cast<const ulonglong2*>(sWl + k * D_OUTP);
                const ulonglong2* wr = reinterpret_cast<const ulonglong2*>(sWr + k * D_OUTP);
#pragma unroll
                for (int jp = 0; jp < D_OUTP / 4; jp++) {
                    ulonglong2 w1 = wl[jp];
                    ulonglong2 w2 = wr[jp];
                    acc[2 * jp]     = fma2(a2v, w1.x, acc[2 * jp]);
                    acc[2 * jp + 1] = fma2(a2v, w1.y, acc[2 * jp + 1]);
                    acc[2 * jp]     = fma2(h2v, w2.x, acc[2 * jp]);
                    acc[2 * jp + 1] = fma2(h2v, w2.y, acc[2 * jp + 1]);
                }
            }
        }
        float* row = sOut + threadIdx.x * D_OUT;
#pragma unroll
        for (int jp = 0; jp < D_OUT / 2; jp++) {
            float lo, hi;
            unpack2(acc[jp], lo, hi);
            row[2 * jp] = lo;
            row[2 * jp + 1] = hi;
        }
        {
            float lo, hi;
            unpack2(acc[D_OUT / 2], lo, hi);
            row[D_OUT - 1] = lo;   // j = 40
        }
        // zero the histogram for the next run (replaces memset node)
        g_cnt[n] = 0;
    }
    __syncthreads();

    int nvalid = min(OUT_BLK, N_NODES - blockIdx.x * OUT_BLK);
    int nfl = nvalid * D_OUT;
    float4* dst = reinterpret_cast<float4*>(out + (size_t)blockIdx.x * OUT_BLK * D_OUT);
    const float4* src = reinterpret_cast<const float4*>(sOut);
    for (int i = threadIdx.x; i < (nfl >> 2); i += blockDim.x)
        dst[i] = src[i];
    for (int i = (nfl & ~3) + threadIdx.x; i < nfl; i += blockDim.x)
        out[(size_t)blockIdx.x * OUT_BLK * D_OUT + i] = sOut[i];
}

// ---------------- launch ------------------------------------------------------
extern "C" void kernel_launch(void* const* d_in, const int* in_sizes, int n_in,
                              void* d_out, int out_size) {
    const float* x   = (const float*)d_in[0];
    const int*   ei  = (const int*)d_in[1];   // int32 [2, E]
    const float* W1l = (const float*)d_in[2];
    const float* b1  = (const float*)d_in[3];
    const float* W1r = (const float*)d_in[4];
    const float* W2l = (const float*)d_in[5];
    const float* b2  = (const float*)d_in[6];
    const float* W2r = (const float*)d_in[7];
    float* out = (float*)d_out;

    static cudaStream_t s_side = nullptr;
    static cudaEvent_t  ev_fork = nullptr;
    static cudaEvent_t  ev_join = nullptr;
    if (s_side == nullptr) {
        cudaStreamCreateWithFlags(&s_side, cudaStreamNonBlocking);
        cudaEventCreateWithFlags(&ev_fork, cudaEventDisableTiming);
        cudaEventCreateWithFlags(&ev_join, cudaEventDisableTiming);
    }

    // fork: transform1 (independent of adjacency build) on the side stream
    cudaEventRecord(ev_fork, 0);
    cudaStreamWaitEvent(s_side, ev_fork, 0);
    k_transform1<<<(N_NODES + 127) / 128, 128, 0, s_side>>>(x, W1l, W1r, b1);
    cudaEventRecord(ev_join, s_side);

    // adjacency build: one scatter pass (counts + padded adjacency).
    // g_cnt is zeroed by the previous run's k_out epilogue (zero-init first).
    k_scatter<<<(N_EDGES + 255) / 256, 256>>>(ei);

    // join: aggregation needs both adjacency and y1l/y1r
    cudaStreamWaitEvent(0, ev_join, 0);
    k_aggregate1<<<(N_NODES * 32 + 255) / 256, 256>>>();

    // Layer 2: gather, then thread-per-node packed GEMV (+ g_cnt re-zero)
    k_aggregate2<<<(N_NODES * 32 + 255) / 256, 256>>>();
    k_out<<<(N_NODES + OUT_BLK - 1) / OUT_BLK, OUT_BLK>>>(W2l, W2r, b2, out);
}